// round 1
// baseline (speedup 1.0000x reference)
#include <cuda_runtime.h>
#include <cstdint>

// ---------------------------------------------------------------------------
// Multi-scale deformable attention, fp32 baseline.
// B=8, C=256, H=8 heads, d=32, Lv=4 levels, P=4 points
// levels: (100,100),(50,50),(25,25),(13,13) -> L = Nq = 13294
//
// Stage 1: value  = input_flatten @ W_val  + b_val        [B*L, 256]
// Stage 2: offattn = query @ [W_off | W_attn] + bias      [B*Nq, 384]
// Stage 3: sampling (softmax + bilinear gather)           [B*Nq, 256]
// Stage 4: out    = outpre @ W_out + b_out  -> d_out      [B*Nq, 256]
// ---------------------------------------------------------------------------

#define BATCH 8
#define CDIM  256
#define NHEAD 8
#define HDIM  32
#define NLVL  4
#define NPNT  4
#define LTOT  13294            // 10000 + 2500 + 625 + 169
#define NQ    LTOT
#define MROWS (BATCH * NQ)     // 106352
#define NOA   384              // 256 (off) + 128 (attn)

// level geometry (compile-time)
__device__ __constant__ int c_lvlW[NLVL]     = {100, 50, 25, 13};
__device__ __constant__ int c_lvlH[NLVL]     = {100, 50, 25, 13};
__device__ __constant__ int c_lvlStart[NLVL] = {0, 10000, 12500, 13125};

// scratch (device globals: allocation-free per harness rules)
__device__ __align__(16) float g_value  [(size_t)MROWS * CDIM];   // 108.9 MB
__device__ __align__(16) float g_offattn[(size_t)MROWS * NOA];    // 163.4 MB
__device__ __align__(16) float g_outpre [(size_t)MROWS * CDIM];   // 108.9 MB
__device__ __align__(16) float g_Wcat   [CDIM * NOA];
__device__ __align__(16) float g_bcat   [NOA];

// ---------------------------------------------------------------------------
// Pack [W_off | W_attn] and [b_off | b_attn] into contiguous 256x384 / 384.
// ---------------------------------------------------------------------------
__global__ void pack_weights(const float* __restrict__ Woff,
                             const float* __restrict__ boff,
                             const float* __restrict__ Wattn,
                             const float* __restrict__ battn) {
    int i = blockIdx.x * blockDim.x + threadIdx.x;
    if (i < CDIM * NOA) {
        int k = i / NOA, n = i % NOA;
        g_Wcat[i] = (n < 256) ? Woff[k * 256 + n] : Wattn[k * 128 + (n - 256)];
    }
    if (i < NOA) {
        g_bcat[i] = (i < 256) ? boff[i] : battn[i - 256];
    }
}

// ---------------------------------------------------------------------------
// Tiled fp32 GEMM: C[M,N] = A[M,256] @ W[256,N] + bias[N]
// BM=BN=128, BK=16, 256 threads, 8x8 per thread.
// M may be ragged (row clamp on loads, guard on stores). N % 128 == 0.
// ---------------------------------------------------------------------------
__global__ __launch_bounds__(256, 2)
void sgemm_bias(const float* __restrict__ A, const float* __restrict__ W,
                const float* __restrict__ bias, float* __restrict__ C,
                int M, int N) {
    constexpr int BM = 128, BN = 128, BK = 16, TM = 8, TN = 8;
    __shared__ float As[BK][BM + 4];
    __shared__ float Ws[BK][BN];

    const int tid = threadIdx.x;
    const int tx = tid & 15;         // 0..15 -> N direction
    const int ty = tid >> 4;         // 0..15 -> M direction
    const int bm = blockIdx.y * BM;
    const int bn = blockIdx.x * BN;

    // A-tile load map: thread -> (row = tid/4 [+64], 4 consecutive k)
    const int arow = tid >> 2;            // 0..63
    const int acol = (tid & 3) * 4;       // 0,4,8,12
    // W-tile load map: thread -> (k-row = tid/32 [+8], 4 consecutive n)
    const int wrow = tid >> 5;            // 0..7
    const int wcol = (tid & 31) * 4;      // 0..124

    float acc[TM][TN];
#pragma unroll
    for (int i = 0; i < TM; i++)
#pragma unroll
        for (int j = 0; j < TN; j++) acc[i][j] = 0.f;

    for (int k0 = 0; k0 < CDIM; k0 += BK) {
        // load A tile (transposed into As[k][m])
#pragma unroll
        for (int i = 0; i < 2; i++) {
            int r = arow + i * 64;
            int gr = bm + r;
            if (gr >= M) gr = M - 1;                     // clamp (stores guarded)
            float4 v = *reinterpret_cast<const float4*>(A + (size_t)gr * CDIM + k0 + acol);
            As[acol + 0][r] = v.x;
            As[acol + 1][r] = v.y;
            As[acol + 2][r] = v.z;
            As[acol + 3][r] = v.w;
        }
        // load W tile
#pragma unroll
        for (int i = 0; i < 2; i++) {
            int r = wrow + i * 8;
            *reinterpret_cast<float4*>(&Ws[r][wcol]) =
                *reinterpret_cast<const float4*>(W + (size_t)(k0 + r) * N + bn + wcol);
        }
        __syncthreads();

#pragma unroll
        for (int k = 0; k < BK; k++) {
            float a[TM], w[TN];
            float4 a0 = *reinterpret_cast<const float4*>(&As[k][ty * TM]);
            float4 a1 = *reinterpret_cast<const float4*>(&As[k][ty * TM + 4]);
            float4 w0 = *reinterpret_cast<const float4*>(&Ws[k][tx * TN]);
            float4 w1 = *reinterpret_cast<const float4*>(&Ws[k][tx * TN + 4]);
            a[0]=a0.x; a[1]=a0.y; a[2]=a0.z; a[3]=a0.w;
            a[4]=a1.x; a[5]=a1.y; a[6]=a1.z; a[7]=a1.w;
            w[0]=w0.x; w[1]=w0.y; w[2]=w0.z; w[3]=w0.w;
            w[4]=w1.x; w[5]=w1.y; w[6]=w1.z; w[7]=w1.w;
#pragma unroll
            for (int i = 0; i < TM; i++)
#pragma unroll
                for (int j = 0; j < TN; j++)
                    acc[i][j] = fmaf(a[i], w[j], acc[i][j]);
        }
        __syncthreads();
    }

    // epilogue: bias + store
#pragma unroll
    for (int i = 0; i < TM; i++) {
        int gr = bm + ty * TM + i;
        if (gr < M) {
#pragma unroll
            for (int j = 0; j < TN; j += 4) {
                int gc = bn + tx * TN + j;
                float4 v;
                v.x = acc[i][j + 0] + bias[gc + 0];
                v.y = acc[i][j + 1] + bias[gc + 1];
                v.z = acc[i][j + 2] + bias[gc + 2];
                v.w = acc[i][j + 3] + bias[gc + 3];
                *reinterpret_cast<float4*>(C + (size_t)gr * N + gc) = v;
            }
        }
    }
}

// ---------------------------------------------------------------------------
// Sampling: one warp per (b, q, h); lane = channel j within head (d = 32).
// Softmax over 16 attention logits in-warp, then 4 levels x 4 points x
// 4 bilinear corners; each corner gather is one coalesced 128B line.
// ---------------------------------------------------------------------------
__global__ __launch_bounds__(256)
void msda_sample(const float* __restrict__ refpts) {
    const unsigned FULL = 0xFFFFFFFFu;
    int gwarp = (blockIdx.x * blockDim.x + threadIdx.x) >> 5;
    int lane = threadIdx.x & 31;
    if (gwarp >= MROWS * NHEAD) return;

    const int h  = gwarp & (NHEAD - 1);
    const int bq = gwarp >> 3;            // b*NQ + q
    const int b  = bq / NQ;

    const float* oa = g_offattn + (size_t)bq * NOA;

    // per-lane offset value (32 offsets for this head: l*8 + p*2 + c)
    float offv = oa[h * 32 + lane];

    // softmax over the 16 logits of this head
    float logit = (lane < 16) ? oa[256 + h * 16 + lane] : -1e30f;
    float m = logit;
#pragma unroll
    for (int s = 16; s > 0; s >>= 1) m = fmaxf(m, __shfl_xor_sync(FULL, m, s));
    float e = (lane < 16) ? __expf(logit - m) : 0.f;
    float ssum = e;
#pragma unroll
    for (int s = 16; s > 0; s >>= 1) ssum += __shfl_xor_sync(FULL, ssum, s);
    float aw = e / ssum;

    const float* vbase = g_value + (size_t)b * ((size_t)LTOT * CDIM) + h * HDIM + lane;
    const float* rp = refpts + (size_t)bq * (NLVL * 2);

    float acc = 0.f;
#pragma unroll
    for (int l = 0; l < NLVL; l++) {
        const float rx = __ldg(rp + l * 2 + 0);
        const float ry = __ldg(rp + l * 2 + 1);
        const int Wl = c_lvlW[l], Hl = c_lvlH[l];
        const int lstart = c_lvlStart[l];
#pragma unroll
        for (int p = 0; p < NPNT; p++) {
            float ox = __shfl_sync(FULL, offv, l * 8 + p * 2 + 0);
            float oy = __shfl_sync(FULL, offv, l * 8 + p * 2 + 1);
            float a  = __shfl_sync(FULL, aw,   l * 4 + p);
            float x = (rx + ox) * (float)Wl - 0.5f;
            float y = (ry + oy) * (float)Hl - 0.5f;
            float xf = floorf(x), yf = floorf(y);
            float fx = x - xf, fy = y - yf;
            int x0 = (int)xf, y0 = (int)yf;

            float sv = 0.f;
#pragma unroll
            for (int dy = 0; dy < 2; dy++) {
#pragma unroll
                for (int dx = 0; dx < 2; dx++) {
                    int xi = x0 + dx, yi = y0 + dy;
                    if (xi >= 0 && xi < Wl && yi >= 0 && yi < Hl) {
                        float wgt = (dx ? fx : 1.f - fx) * (dy ? fy : 1.f - fy);
                        sv = fmaf(wgt,
                                  __ldg(vbase + (size_t)(lstart + yi * Wl + xi) * CDIM),
                                  sv);
                    }
                }
            }
            acc = fmaf(a, sv, acc);
        }
    }
    g_outpre[(size_t)bq * CDIM + h * HDIM + lane] = acc;
}

// ---------------------------------------------------------------------------
// launch
// ---------------------------------------------------------------------------
extern "C" void kernel_launch(void* const* d_in, const int* in_sizes, int n_in,
                              void* d_out, int out_size) {
    const float* query   = (const float*)d_in[0];
    const float* refpts  = (const float*)d_in[1];
    const float* inflat  = (const float*)d_in[2];
    // d_in[3] = input_spatial_shapes (compile-time constants here)
    const float* W_off   = (const float*)d_in[4];
    const float* b_off   = (const float*)d_in[5];
    const float* W_attn  = (const float*)d_in[6];
    const float* b_attn  = (const float*)d_in[7];
    const float* W_val   = (const float*)d_in[8];
    const float* b_val   = (const float*)d_in[9];
    const float* W_out   = (const float*)d_in[10];
    const float* b_out   = (const float*)d_in[11];
    float* out = (float*)d_out;

    float *valp, *oap, *prep;
    cudaGetSymbolAddress((void**)&valp, g_value);
    cudaGetSymbolAddress((void**)&oap,  g_offattn);
    cudaGetSymbolAddress((void**)&prep, g_outpre);
    float *wcatp, *bcatp;
    cudaGetSymbolAddress((void**)&wcatp, g_Wcat);
    cudaGetSymbolAddress((void**)&bcatp, g_bcat);

    // 1. pack off|attn weights
    pack_weights<<<(CDIM * NOA + 255) / 256, 256>>>(W_off, b_off, W_attn, b_attn);

    const int mblocks = (MROWS + 127) / 128;   // 831

    // 2. value GEMM: [M,256] @ [256,256]
    sgemm_bias<<<dim3(CDIM / 128, mblocks), 256>>>(inflat, W_val, b_val, valp,
                                                   MROWS, CDIM);
    // 3. off|attn GEMM: [M,256] @ [256,384]
    sgemm_bias<<<dim3(NOA / 128, mblocks), 256>>>(query, wcatp, bcatp, oap,
                                                  MROWS, NOA);
    // 4. sampling: one warp per (b,q,h)
    {
        long long nwarps = (long long)MROWS * NHEAD;         // 850,816
        int blocks = (int)((nwarps * 32 + 255) / 256);       // 106,352
        msda_sample<<<blocks, 256>>>(refpts);
    }
    // 5. output GEMM -> d_out
    sgemm_bias<<<dim3(CDIM / 128, mblocks), 256>>>(prep, W_out, b_out, out,
                                                   MROWS, CDIM);
}

// round 2
// speedup vs baseline: 1.4329x; 1.4329x over previous
#include <cuda_runtime.h>
#include <cuda_fp16.h>
#include <cstdint>

// ---------------------------------------------------------------------------
// Multi-scale deformable attention.
// B=8, C=256, H=8 heads, d=32, Lv=4 levels, P=4 points
// levels: (100,100),(50,50),(25,25),(13,13) -> L = Nq = 13294
//
// Stage 1: value  = half(input_flatten @ W_val + b_val)   [B*L, 256] fp16
// Stage 2: offattn = query @ [W_off | W_attn] + bias      [B*Nq, 384] fp32
// Stage 3: sampling (softmax + bilinear gather)           [B*Nq, 256] fp32
//          one warp per (b,q); lane = head*4 + sub; 8 ch per lane
// Stage 4: out    = outpre @ W_out + b_out  -> d_out      [B*Nq, 256]
// ---------------------------------------------------------------------------

#define BATCH 8
#define CDIM  256
#define NHEAD 8
#define HDIM  32
#define NLVL  4
#define NPNT  4
#define LTOT  13294            // 10000 + 2500 + 625 + 169
#define NQ    LTOT
#define MROWS (BATCH * NQ)     // 106352
#define NOA   384              // 256 (off) + 128 (attn)

// scratch (device globals: allocation-free per harness rules)
__device__ __align__(16) __half g_value_h[(size_t)MROWS * CDIM];  // 54.5 MB
__device__ __align__(16) float g_offattn[(size_t)MROWS * NOA];    // 163.4 MB
__device__ __align__(16) float g_outpre [(size_t)MROWS * CDIM];   // 108.9 MB
__device__ __align__(16) float g_Wcat   [CDIM * NOA];
__device__ __align__(16) float g_bcat   [NOA];

// ---------------------------------------------------------------------------
// Pack [W_off | W_attn] and [b_off | b_attn] into contiguous 256x384 / 384.
// ---------------------------------------------------------------------------
__global__ void pack_weights(const float* __restrict__ Woff,
                             const float* __restrict__ boff,
                             const float* __restrict__ Wattn,
                             const float* __restrict__ battn) {
    int i = blockIdx.x * blockDim.x + threadIdx.x;
    if (i < CDIM * NOA) {
        int k = i / NOA, n = i % NOA;
        g_Wcat[i] = (n < 256) ? Woff[k * 256 + n] : Wattn[k * 128 + (n - 256)];
    }
    if (i < NOA) {
        g_bcat[i] = (i < 256) ? boff[i] : battn[i - 256];
    }
}

// ---------------------------------------------------------------------------
// Tiled fp32 GEMM: C[M,N] = A[M,256] @ W[256,N] + bias[N]
// BM=BN=128, BK=16, 256 threads, 8x8 per thread. Optional fp16 output.
// ---------------------------------------------------------------------------
template<int OUT_HALF>
__global__ __launch_bounds__(256, 2)
void sgemm_bias(const float* __restrict__ A, const float* __restrict__ W,
                const float* __restrict__ bias, void* __restrict__ Cv,
                int M, int N) {
    constexpr int BM = 128, BN = 128, BK = 16, TM = 8, TN = 8;
    __shared__ float As[BK][BM + 4];
    __shared__ float Ws[BK][BN];

    const int tid = threadIdx.x;
    const int tx = tid & 15;
    const int ty = tid >> 4;
    const int bm = blockIdx.y * BM;
    const int bn = blockIdx.x * BN;

    const int arow = tid >> 2;
    const int acol = (tid & 3) * 4;
    const int wrow = tid >> 5;
    const int wcol = (tid & 31) * 4;

    float acc[TM][TN];
#pragma unroll
    for (int i = 0; i < TM; i++)
#pragma unroll
        for (int j = 0; j < TN; j++) acc[i][j] = 0.f;

    for (int k0 = 0; k0 < CDIM; k0 += BK) {
#pragma unroll
        for (int i = 0; i < 2; i++) {
            int r = arow + i * 64;
            int gr = bm + r;
            if (gr >= M) gr = M - 1;
            float4 v = *reinterpret_cast<const float4*>(A + (size_t)gr * CDIM + k0 + acol);
            As[acol + 0][r] = v.x;
            As[acol + 1][r] = v.y;
            As[acol + 2][r] = v.z;
            As[acol + 3][r] = v.w;
        }
#pragma unroll
        for (int i = 0; i < 2; i++) {
            int r = wrow + i * 8;
            *reinterpret_cast<float4*>(&Ws[r][wcol]) =
                *reinterpret_cast<const float4*>(W + (size_t)(k0 + r) * N + bn + wcol);
        }
        __syncthreads();

#pragma unroll
        for (int k = 0; k < BK; k++) {
            float a[TM], w[TN];
            float4 a0 = *reinterpret_cast<const float4*>(&As[k][ty * TM]);
            float4 a1 = *reinterpret_cast<const float4*>(&As[k][ty * TM + 4]);
            float4 w0 = *reinterpret_cast<const float4*>(&Ws[k][tx * TN]);
            float4 w1 = *reinterpret_cast<const float4*>(&Ws[k][tx * TN + 4]);
            a[0]=a0.x; a[1]=a0.y; a[2]=a0.z; a[3]=a0.w;
            a[4]=a1.x; a[5]=a1.y; a[6]=a1.z; a[7]=a1.w;
            w[0]=w0.x; w[1]=w0.y; w[2]=w0.z; w[3]=w0.w;
            w[4]=w1.x; w[5]=w1.y; w[6]=w1.z; w[7]=w1.w;
#pragma unroll
            for (int i = 0; i < TM; i++)
#pragma unroll
                for (int j = 0; j < TN; j++)
                    acc[i][j] = fmaf(a[i], w[j], acc[i][j]);
        }
        __syncthreads();
    }

#pragma unroll
    for (int i = 0; i < TM; i++) {
        int gr = bm + ty * TM + i;
        if (gr < M) {
            if (OUT_HALF) {
                __half hb[8];
#pragma unroll
                for (int j = 0; j < TN; j++)
                    hb[j] = __float2half_rn(acc[i][j] + bias[bn + tx * TN + j]);
                *reinterpret_cast<uint4*>((__half*)Cv + (size_t)gr * N + bn + tx * TN) =
                    *reinterpret_cast<uint4*>(hb);
            } else {
#pragma unroll
                for (int j = 0; j < TN; j += 4) {
                    int gc = bn + tx * TN + j;
                    float4 v;
                    v.x = acc[i][j + 0] + bias[gc + 0];
                    v.y = acc[i][j + 1] + bias[gc + 1];
                    v.z = acc[i][j + 2] + bias[gc + 2];
                    v.w = acc[i][j + 3] + bias[gc + 3];
                    *reinterpret_cast<float4*>((float*)Cv + (size_t)gr * N + gc) = v;
                }
            }
        }
    }
}

// ---------------------------------------------------------------------------
// Sampling v2: one warp per (b,q), all 8 heads at once.
// lane = h*4 + sub ; each lane accumulates channels [h*32 + sub*8 .. +8).
// Offsets + softmaxed attention weights staged in padded smem (no shuffles
// in the hot loop). Value tensor is fp16; gathers are 16B per lane (uint4).
// ---------------------------------------------------------------------------
#define WARPS_PER_BLK 8
#define OFF_STRIDE 36   // 8 heads * 36 floats, bank-conflict-free
#define AW_STRIDE  20

__global__ __launch_bounds__(256)
void msda_sample(const float* __restrict__ refpts) {
    constexpr int WL[NLVL] = {100, 50, 25, 13};
    constexpr int HL[NLVL] = {100, 50, 25, 13};
    constexpr int ST[NLVL] = {0, 10000, 12500, 13125};
    const unsigned FULL = 0xFFFFFFFFu;

    __shared__ float off_s[WARPS_PER_BLK][NHEAD * OFF_STRIDE];
    __shared__ float aw_s [WARPS_PER_BLK][NHEAD * AW_STRIDE];

    const int w    = threadIdx.x >> 5;
    const int lane = threadIdx.x & 31;
    const int bq   = blockIdx.x * WARPS_PER_BLK + w;   // grid exactly covers MROWS
    const int b    = bq / NQ;
    const int h    = lane >> 2;
    const int sub  = lane & 3;

    const float* oa = g_offattn + (size_t)bq * NOA;

    // ---- stage offsets: 256 floats -> padded smem [h][32] ----
#pragma unroll
    for (int j0 = 0; j0 < 8; j0 += 4) {
        int o = lane * 8 + j0;                    // multiple of 4, stays in one head
        float4 v = *reinterpret_cast<const float4*>(oa + o);
        float* dst = &off_s[w][(o >> 5) * OFF_STRIDE + (o & 31)];
        dst[0] = v.x; dst[1] = v.y; dst[2] = v.z; dst[3] = v.w;
    }

    // ---- softmax over 16 logits per head; 4 lanes per head ----
    {
        const float* lg = oa + 256 + h * 16 + sub * 4;
        float l0 = lg[0], l1 = lg[1], l2 = lg[2], l3 = lg[3];
        float m = fmaxf(fmaxf(l0, l1), fmaxf(l2, l3));
        m = fmaxf(m, __shfl_xor_sync(FULL, m, 1));
        m = fmaxf(m, __shfl_xor_sync(FULL, m, 2));
        float e0 = __expf(l0 - m), e1 = __expf(l1 - m);
        float e2 = __expf(l2 - m), e3 = __expf(l3 - m);
        float s = e0 + e1 + e2 + e3;
        s += __shfl_xor_sync(FULL, s, 1);
        s += __shfl_xor_sync(FULL, s, 2);
        float inv = __frcp_rn(s);
        float* dst = &aw_s[w][h * AW_STRIDE + sub * 4];
        dst[0] = e0 * inv; dst[1] = e1 * inv; dst[2] = e2 * inv; dst[3] = e3 * inv;
    }
    __syncwarp();

    // reference points: 8 floats per (b,q); broadcast from lanes 0..7
    float rpv = (lane < 8) ? __ldg(refpts + (size_t)bq * 8 + lane) : 0.f;

    const float* offp = &off_s[w][h * OFF_STRIDE];
    const float* awp  = &aw_s[w][h * AW_STRIDE];
    const __half* vhead = g_value_h + (size_t)b * ((size_t)LTOT * CDIM)
                        + h * HDIM + sub * 8;

    float acc[8];
#pragma unroll
    for (int k = 0; k < 8; k++) acc[k] = 0.f;

#pragma unroll
    for (int l = 0; l < NLVL; l++) {
        const float rx = __shfl_sync(FULL, rpv, l * 2 + 0);
        const float ry = __shfl_sync(FULL, rpv, l * 2 + 1);
        const int Wl = WL[l], Hl = HL[l], lstart = ST[l];
        const float fW = (float)Wl, fH = (float)Hl;
#pragma unroll
        for (int p = 0; p < NPNT; p++) {
            const float ox = offp[l * 8 + p * 2 + 0];
            const float oy = offp[l * 8 + p * 2 + 1];
            const float a  = awp[l * 4 + p];

            float x = (rx + ox) * fW - 0.5f;
            float y = (ry + oy) * fH - 0.5f;
            float xf = floorf(x), yf = floorf(y);
            float fx = x - xf, fy = y - yf;
            int x0 = (int)xf, y0 = (int)yf;

            float ay0 = a * (1.f - fy), ay1 = a * fy;
            float w00 = ay0 * (1.f - fx), w01 = ay0 * fx;
            float w10 = ay1 * (1.f - fx), w11 = ay1 * fx;

#define CORNER(XI, YI, WT)                                                     \
            {                                                                  \
                int xi = (XI), yi = (YI);                                      \
                if ((unsigned)xi < (unsigned)Wl && (unsigned)yi < (unsigned)Hl) { \
                    const __half* p_ = vhead +                                 \
                        ((size_t)(lstart + yi * Wl + xi) << 8);                \
                    uint4 raw = *reinterpret_cast<const uint4*>(p_);           \
                    float2 f0 = __half22float2(*reinterpret_cast<__half2*>(&raw.x)); \
                    float2 f1 = __half22float2(*reinterpret_cast<__half2*>(&raw.y)); \
                    float2 f2 = __half22float2(*reinterpret_cast<__half2*>(&raw.z)); \
                    float2 f3 = __half22float2(*reinterpret_cast<__half2*>(&raw.w)); \
                    acc[0] = fmaf(WT, f0.x, acc[0]);                           \
                    acc[1] = fmaf(WT, f0.y, acc[1]);                           \
                    acc[2] = fmaf(WT, f1.x, acc[2]);                           \
                    acc[3] = fmaf(WT, f1.y, acc[3]);                           \
                    acc[4] = fmaf(WT, f2.x, acc[4]);                           \
                    acc[5] = fmaf(WT, f2.y, acc[5]);                           \
                    acc[6] = fmaf(WT, f3.x, acc[6]);                           \
                    acc[7] = fmaf(WT, f3.y, acc[7]);                           \
                }                                                              \
            }
            CORNER(x0,     y0,     w00)
            CORNER(x0 + 1, y0,     w01)
            CORNER(x0,     y0 + 1, w10)
            CORNER(x0 + 1, y0 + 1, w11)
#undef CORNER
        }
    }

    float* out = g_outpre + (size_t)bq * CDIM + h * HDIM + sub * 8;
    *reinterpret_cast<float4*>(out)     = make_float4(acc[0], acc[1], acc[2], acc[3]);
    *reinterpret_cast<float4*>(out + 4) = make_float4(acc[4], acc[5], acc[6], acc[7]);
}

// ---------------------------------------------------------------------------
// launch
// ---------------------------------------------------------------------------
extern "C" void kernel_launch(void* const* d_in, const int* in_sizes, int n_in,
                              void* d_out, int out_size) {
    const float* query   = (const float*)d_in[0];
    const float* refpts  = (const float*)d_in[1];
    const float* inflat  = (const float*)d_in[2];
    // d_in[3] = input_spatial_shapes (compile-time constants here)
    const float* W_off   = (const float*)d_in[4];
    const float* b_off   = (const float*)d_in[5];
    const float* W_attn  = (const float*)d_in[6];
    const float* b_attn  = (const float*)d_in[7];
    const float* W_val   = (const float*)d_in[8];
    const float* b_val   = (const float*)d_in[9];
    const float* W_out   = (const float*)d_in[10];
    const float* b_out   = (const float*)d_in[11];
    float* out = (float*)d_out;

    void *valh, *oap, *prep, *wcatp, *bcatp;
    cudaGetSymbolAddress(&valh,  g_value_h);
    cudaGetSymbolAddress(&oap,   g_offattn);
    cudaGetSymbolAddress(&prep,  g_outpre);
    cudaGetSymbolAddress(&wcatp, g_Wcat);
    cudaGetSymbolAddress(&bcatp, g_bcat);

    // 1. pack off|attn weights
    pack_weights<<<(CDIM * NOA + 255) / 256, 256>>>(W_off, b_off, W_attn, b_attn);

    const int mblocks = (MROWS + 127) / 128;   // 831

    // 2. value GEMM -> fp16: [M,256] @ [256,256]
    sgemm_bias<1><<<dim3(CDIM / 128, mblocks), 256>>>(inflat, W_val, b_val, valh,
                                                      MROWS, CDIM);
    // 3. off|attn GEMM: [M,256] @ [256,384]
    sgemm_bias<0><<<dim3(NOA / 128, mblocks), 256>>>(query, (const float*)wcatp,
                                                     (const float*)bcatp, oap,
                                                     MROWS, NOA);
    // 4. sampling: one warp per (b,q)
    msda_sample<<<MROWS / WARPS_PER_BLK, 256>>>(refpts);

    // 5. output GEMM -> d_out
    sgemm_bias<0><<<dim3(CDIM / 128, mblocks), 256>>>((const float*)prep, W_out,
                                                      b_out, out, MROWS, CDIM);
}

// round 5
// speedup vs baseline: 2.6698x; 1.8632x over previous
#include <cuda_runtime.h>
#include <cuda_fp16.h>
#include <cuda_bf16.h>
#include <cstdint>

// ---------------------------------------------------------------------------
// Multi-scale deformable attention — bf16 split GEMMs on mma.sync (HMMA).
// (tcgen05 unavailable: toolchain targets sm_100 without the 'a' feature set.)
// B=8, C=256, H=8, d=32, Lv=4, P=4, L=Nq=13294, M = 106352
//
//  split:   X = X_hi(bf16) + X_lo(bf16); A@B ~ Ahi*Bhi + Ahi*Blo + Alo*Bhi
//  Stage 1: value  = fp16(in @ W_val + b)         [M,256]
//  Stage 2: offattn = q @ [W_off|W_attn] + b      [M,384] fp32
//  Stage 3: sampling -> pre_hi/pre_lo (bf16)      [M,256]
//  Stage 4: out = pre @ W_out + b -> d_out        [M,256] fp32
// ---------------------------------------------------------------------------

#define BATCH 8
#define CDIM  256
#define NHEAD 8
#define HDIM  32
#define NLVL  4
#define NPNT  4
#define LTOT  13294
#define NQ    LTOT
#define MROWS (BATCH * NQ)     // 106352
#define NOA   384

// ------------------------------ device scratch -----------------------------
__device__ __align__(16) __nv_bfloat16 g_q_hi [(size_t)MROWS * CDIM];
__device__ __align__(16) __nv_bfloat16 g_q_lo [(size_t)MROWS * CDIM];
__device__ __align__(16) __nv_bfloat16 g_in_hi[(size_t)MROWS * CDIM];
__device__ __align__(16) __nv_bfloat16 g_in_lo[(size_t)MROWS * CDIM];
__device__ __align__(16) __nv_bfloat16 g_pre_hi[(size_t)MROWS * CDIM];
__device__ __align__(16) __nv_bfloat16 g_pre_lo[(size_t)MROWS * CDIM];
__device__ __align__(16) __half g_value_h[(size_t)MROWS * CDIM];
__device__ __align__(16) float  g_offattn[(size_t)MROWS * NOA];
// weights transposed to [N][K=256] bf16 hi/lo
__device__ __align__(16) __nv_bfloat16 g_wval_hi[CDIM * CDIM];
__device__ __align__(16) __nv_bfloat16 g_wval_lo[CDIM * CDIM];
__device__ __align__(16) __nv_bfloat16 g_woa_hi [NOA * CDIM];
__device__ __align__(16) __nv_bfloat16 g_woa_lo [NOA * CDIM];
__device__ __align__(16) __nv_bfloat16 g_wout_hi[CDIM * CDIM];
__device__ __align__(16) __nv_bfloat16 g_wout_lo[CDIM * CDIM];
__device__ __align__(16) float g_bcat[NOA];

// ------------------------------ PTX helpers --------------------------------
__device__ __forceinline__ uint32_t smem_u32(const void* p) {
    uint32_t a;
    asm("{ .reg .u64 t; cvta.to.shared.u64 t, %1; cvt.u32.u64 %0, t; }"
        : "=r"(a) : "l"(p));
    return a;
}

#define CP_ASYNC16(dst, src) \
    asm volatile("cp.async.cg.shared.global [%0], [%1], 16;" \
                 :: "r"(dst), "l"(src) : "memory")
#define CP_COMMIT() asm volatile("cp.async.commit_group;" ::: "memory")
#define CP_WAIT(n)  asm volatile("cp.async.wait_group %0;" :: "n"(n) : "memory")

#define LDSM_X4(r0, r1, r2, r3, a) \
    asm volatile("ldmatrix.sync.aligned.m8n8.x4.shared.b16 {%0,%1,%2,%3}, [%4];" \
                 : "=r"(r0), "=r"(r1), "=r"(r2), "=r"(r3) : "r"(a))

#define MMA16816(d, a0, a1, a2, a3, b0, b1)                                    \
    asm volatile("mma.sync.aligned.m16n8k16.row.col.f32.bf16.bf16.f32 "        \
                 "{%0,%1,%2,%3}, {%4,%5,%6,%7}, {%8,%9}, {%0,%1,%2,%3};"       \
                 : "+f"((d)[0]), "+f"((d)[1]), "+f"((d)[2]), "+f"((d)[3])      \
                 : "r"(a0), "r"(a1), "r"(a2), "r"(a3), "r"(b0), "r"(b1))

// 128B-line swizzle for 64B rows: two rows per line, 8 chunk slots/line.
// row r, chunk c (0..3, 16B each)
__device__ __forceinline__ uint32_t swz(int r, int c) {
    int slot = (((r & 1) << 2) | c) ^ ((r >> 1) & 7);
    return (uint32_t)(((r >> 1) << 7) + (slot << 4));
}

// ------------------------------ prep kernels -------------------------------
__global__ void pack_bias(const float* __restrict__ boff,
                          const float* __restrict__ battn) {
    int i = blockIdx.x * blockDim.x + threadIdx.x;
    if (i < NOA) g_bcat[i] = (i < 256) ? boff[i] : battn[i - 256];
}

// W [256 x Nsrc] row-major -> rows [rowoff..rowoff+Nsrc) of [N][256] hi/lo
__global__ void pack_wt(const float* __restrict__ W, int Nsrc,
                        __nv_bfloat16* __restrict__ hi,
                        __nv_bfloat16* __restrict__ lo, int rowoff) {
    int i = blockIdx.x * blockDim.x + threadIdx.x;
    if (i < 256 * Nsrc) {
        int k = i / Nsrc, n = i % Nsrc;
        float v = W[i];
        __nv_bfloat16 h = __float2bfloat16(v);
        hi[(size_t)(rowoff + n) * 256 + k] = h;
        lo[(size_t)(rowoff + n) * 256 + k] = __float2bfloat16(v - __bfloat162float(h));
    }
}

__global__ void split_a(const float4* __restrict__ src,
                        __nv_bfloat16* __restrict__ hi,
                        __nv_bfloat16* __restrict__ lo, int n4) {
    int i = blockIdx.x * blockDim.x + threadIdx.x;
    if (i >= n4) return;
    float4 v = src[i];
    __nv_bfloat16 h[4], l[4];
    float f[4] = {v.x, v.y, v.z, v.w};
#pragma unroll
    for (int k = 0; k < 4; k++) {
        h[k] = __float2bfloat16(f[k]);
        l[k] = __float2bfloat16(f[k] - __bfloat162float(h[k]));
    }
    *reinterpret_cast<uint2*>(hi + (size_t)i * 4) = *reinterpret_cast<uint2*>(h);
    *reinterpret_cast<uint2*>(lo + (size_t)i * 4) = *reinterpret_cast<uint2*>(l);
}

// ------------------------------ HMMA GEMM ----------------------------------
// C[128,128]-tile of (Ahi+Alo)[M,256] @ (Bhi+Blo)[N,256]^T + bias.
// A,B row-major [rows][256] bf16. grid = (N/128, ceil(M/128)).
// OUT_MODE: 0 = fp32, 1 = fp16.
#define TILE_SZ 8192                 // 128 rows x 32 bf16, swizzled
#define STAGE_SZ (4 * TILE_SZ)       // Ahi, Alo, Bhi, Blo

template<int OUT_MODE>
__global__ __launch_bounds__(256, 2)
void hmma_gemm(const __nv_bfloat16* __restrict__ Ahi,
               const __nv_bfloat16* __restrict__ Alo,
               const __nv_bfloat16* __restrict__ Bhi,
               const __nv_bfloat16* __restrict__ Blo,
               const float* __restrict__ bias,
               void* __restrict__ outp, int M, int ldOut) {
    extern __shared__ __align__(128) char smem[];
    const uint32_t sbase = smem_u32(smem);
    const int tid  = threadIdx.x;
    const int wid  = tid >> 5, lane = tid & 31;
    const int wm   = wid & 3, wn = wid >> 2;       // 4 x 2 warp grid
    const int bm   = blockIdx.y * 128;
    const int ncol0 = blockIdx.x * 128;
    const int rclA = M - 1;

    const __nv_bfloat16* gsrc[4] = {Ahi, Alo, Bhi, Blo};

    // per-thread load map: 2 chunks per tile (512 chunks, 256 threads)
    // chunk = tid + i*256 ; row = chunk>>2 ; c = chunk&3
    auto load_stage = [&](int buf, int kc) {
        const int kofs = kc * 32;
#pragma unroll
        for (int t = 0; t < 4; t++) {
            const __nv_bfloat16* gb = gsrc[t];
            const int row0 = (t < 2) ? bm : ncol0;
            const int rcl  = (t < 2) ? rclA : 0x7FFFFFFF;
            const uint32_t db = sbase + buf * STAGE_SZ + t * TILE_SZ;
#pragma unroll
            for (int i = 0; i < 2; i++) {
                int chunk = tid + i * 256;
                int row = chunk >> 2, c = chunk & 3;
                int gr = row0 + row; if (gr > rcl) gr = rcl;
                CP_ASYNC16(db + swz(row, c),
                           gb + (size_t)gr * 256 + kofs + c * 8);
            }
        }
    };

    float acc[2][8][4];
#pragma unroll
    for (int i = 0; i < 2; i++)
#pragma unroll
        for (int j = 0; j < 8; j++)
#pragma unroll
            for (int q = 0; q < 4; q++) acc[i][j][q] = 0.f;

    load_stage(0, 0);
    CP_COMMIT();

    for (int kc = 0; kc < 8; kc++) {
        const int buf = kc & 1;
        if (kc + 1 < 8) {
            load_stage(buf ^ 1, kc + 1);
            CP_COMMIT();
            CP_WAIT(1);
        } else {
            CP_WAIT(0);
        }
        __syncthreads();

        const uint32_t sAhi = sbase + buf * STAGE_SZ;
        const uint32_t sAlo = sAhi + TILE_SZ;
        const uint32_t sBhi = sAhi + 2 * TILE_SZ;
        const uint32_t sBlo = sAhi + 3 * TILE_SZ;

#pragma unroll
        for (int ks = 0; ks < 2; ks++) {
            // A fragments: 2 m-tiles x (hi, lo)
            uint32_t ahi[2][4], alo[2][4];
#pragma unroll
            for (int i = 0; i < 2; i++) {
                int row = wm * 32 + i * 16 + (lane & 15);
                int c   = ks * 2 + (lane >> 4);
                uint32_t off = swz(row, c);
                LDSM_X4(ahi[i][0], ahi[i][1], ahi[i][2], ahi[i][3], sAhi + off);
                LDSM_X4(alo[i][0], alo[i][1], alo[i][2], alo[i][3], sAlo + off);
            }
            // B: 4 pairs of n-tiles
#pragma unroll
            for (int jj = 0; jj < 4; jj++) {
                int g = lane >> 3, l8 = lane & 7;
                int row = wn * 64 + jj * 16 + ((g >> 1) << 3) + l8;
                int c   = ks * 2 + (g & 1);
                uint32_t off = swz(row, c);
                uint32_t bh0, bh1, bh2, bh3, bl0, bl1, bl2, bl3;
                LDSM_X4(bh0, bh1, bh2, bh3, sBhi + off);
                LDSM_X4(bl0, bl1, bl2, bl3, sBlo + off);
#pragma unroll
                for (int i = 0; i < 2; i++) {
                    MMA16816(acc[i][jj * 2],     ahi[i][0], ahi[i][1], ahi[i][2], ahi[i][3], bh0, bh1);
                    MMA16816(acc[i][jj * 2],     ahi[i][0], ahi[i][1], ahi[i][2], ahi[i][3], bl0, bl1);
                    MMA16816(acc[i][jj * 2],     alo[i][0], alo[i][1], alo[i][2], alo[i][3], bh0, bh1);
                    MMA16816(acc[i][jj * 2 + 1], ahi[i][0], ahi[i][1], ahi[i][2], ahi[i][3], bh2, bh3);
                    MMA16816(acc[i][jj * 2 + 1], ahi[i][0], ahi[i][1], ahi[i][2], ahi[i][3], bl2, bl3);
                    MMA16816(acc[i][jj * 2 + 1], alo[i][0], alo[i][1], alo[i][2], alo[i][3], bh2, bh3);
                }
            }
        }
        __syncthreads();
    }

    // ---- epilogue: direct global stores + bias ----
#pragma unroll
    for (int i = 0; i < 2; i++) {
        int r0 = bm + wm * 32 + i * 16 + (lane >> 2);
        int r1 = r0 + 8;
#pragma unroll
        for (int j = 0; j < 8; j++) {
            int gc = ncol0 + wn * 64 + j * 8 + (lane & 3) * 2;
            float b0 = __ldg(bias + gc), b1 = __ldg(bias + gc + 1);
            float v00 = acc[i][j][0] + b0, v01 = acc[i][j][1] + b1;
            float v10 = acc[i][j][2] + b0, v11 = acc[i][j][3] + b1;
            if (OUT_MODE == 1) {
                __half* o = (__half*)outp;
                if (r0 < M)
                    *reinterpret_cast<__half2*>(o + (size_t)r0 * ldOut + gc) =
                        __floats2half2_rn(v00, v01);
                if (r1 < M)
                    *reinterpret_cast<__half2*>(o + (size_t)r1 * ldOut + gc) =
                        __floats2half2_rn(v10, v11);
            } else {
                float* o = (float*)outp;
                if (r0 < M)
                    *reinterpret_cast<float2*>(o + (size_t)r0 * ldOut + gc) =
                        make_float2(v00, v01);
                if (r1 < M)
                    *reinterpret_cast<float2*>(o + (size_t)r1 * ldOut + gc) =
                        make_float2(v10, v11);
            }
        }
    }
}

// ------------------------------ sampler ------------------------------------
#define WARPS_PER_BLK 8
#define OFF_STRIDE 36
#define AW_STRIDE  20

__global__ __launch_bounds__(256)
void msda_sample(const float* __restrict__ refpts) {
    constexpr int WL[NLVL] = {100, 50, 25, 13};
    constexpr int HL[NLVL] = {100, 50, 25, 13};
    constexpr int ST[NLVL] = {0, 10000, 12500, 13125};
    const unsigned FULL = 0xFFFFFFFFu;

    __shared__ float off_s[WARPS_PER_BLK][NHEAD * OFF_STRIDE];
    __shared__ float aw_s [WARPS_PER_BLK][NHEAD * AW_STRIDE];

    const int w    = threadIdx.x >> 5;
    const int lane = threadIdx.x & 31;
    const int bq   = blockIdx.x * WARPS_PER_BLK + w;
    const int b    = bq / NQ;
    const int bh   = lane >> 2;
    const int sub  = lane & 3;

    const float* oa = g_offattn + (size_t)bq * NOA;

#pragma unroll
    for (int j0 = 0; j0 < 8; j0 += 4) {
        int o = lane * 8 + j0;
        float4 v = *reinterpret_cast<const float4*>(oa + o);
        float* dst = &off_s[w][(o >> 5) * OFF_STRIDE + (o & 31)];
        dst[0] = v.x; dst[1] = v.y; dst[2] = v.z; dst[3] = v.w;
    }
    {
        const float* lg = oa + 256 + bh * 16 + sub * 4;
        float l0 = lg[0], l1 = lg[1], l2 = lg[2], l3 = lg[3];
        float m = fmaxf(fmaxf(l0, l1), fmaxf(l2, l3));
        m = fmaxf(m, __shfl_xor_sync(FULL, m, 1));
        m = fmaxf(m, __shfl_xor_sync(FULL, m, 2));
        float e0 = __expf(l0 - m), e1 = __expf(l1 - m);
        float e2 = __expf(l2 - m), e3 = __expf(l3 - m);
        float s = e0 + e1 + e2 + e3;
        s += __shfl_xor_sync(FULL, s, 1);
        s += __shfl_xor_sync(FULL, s, 2);
        float inv = __frcp_rn(s);
        float* dst = &aw_s[w][bh * AW_STRIDE + sub * 4];
        dst[0] = e0 * inv; dst[1] = e1 * inv; dst[2] = e2 * inv; dst[3] = e3 * inv;
    }
    __syncwarp();

    float rpv = (lane < 8) ? __ldg(refpts + (size_t)bq * 8 + lane) : 0.f;

    const float* offp = &off_s[w][bh * OFF_STRIDE];
    const float* awp  = &aw_s[w][bh * AW_STRIDE];
    const __half* vhead = g_value_h + (size_t)b * ((size_t)LTOT * CDIM)
                        + bh * HDIM + sub * 8;

    float acc[8];
#pragma unroll
    for (int k = 0; k < 8; k++) acc[k] = 0.f;

#pragma unroll
    for (int l = 0; l < NLVL; l++) {
        const float rx = __shfl_sync(FULL, rpv, l * 2 + 0);
        const float ry = __shfl_sync(FULL, rpv, l * 2 + 1);
        const int Wl = WL[l], Hl = HL[l], lstart = ST[l];
        const float fW = (float)Wl, fH = (float)Hl;
#pragma unroll
        for (int p = 0; p < NPNT; p++) {
            const float ox = offp[l * 8 + p * 2 + 0];
            const float oy = offp[l * 8 + p * 2 + 1];
            const float a  = awp[l * 4 + p];

            float x = (rx + ox) * fW - 0.5f;
            float y = (ry + oy) * fH - 0.5f;
            float xf = floorf(x), yf = floorf(y);
            float fx = x - xf, fy = y - yf;
            int x0 = (int)xf, y0 = (int)yf;

            float ay0 = a * (1.f - fy), ay1 = a * fy;
            float w00 = ay0 * (1.f - fx), w01 = ay0 * fx;
            float w10 = ay1 * (1.f - fx), w11 = ay1 * fx;

#define CORNER(XI, YI, WT)                                                     \
            {                                                                  \
                int xi = (XI), yi = (YI);                                      \
                if ((unsigned)xi < (unsigned)Wl && (unsigned)yi < (unsigned)Hl) { \
                    const __half* p_ = vhead +                                 \
                        ((size_t)(lstart + yi * Wl + xi) << 8);                \
                    uint4 raw = *reinterpret_cast<const uint4*>(p_);           \
                    float2 f0 = __half22float2(*reinterpret_cast<__half2*>(&raw.x)); \
                    float2 f1 = __half22float2(*reinterpret_cast<__half2*>(&raw.y)); \
                    float2 f2 = __half22float2(*reinterpret_cast<__half2*>(&raw.z)); \
                    float2 f3 = __half22float2(*reinterpret_cast<__half2*>(&raw.w)); \
                    acc[0] = fmaf(WT, f0.x, acc[0]);                           \
                    acc[1] = fmaf(WT, f0.y, acc[1]);                           \
                    acc[2] = fmaf(WT, f1.x, acc[2]);                           \
                    acc[3] = fmaf(WT, f1.y, acc[3]);                           \
                    acc[4] = fmaf(WT, f2.x, acc[4]);                           \
                    acc[5] = fmaf(WT, f2.y, acc[5]);                           \
                    acc[6] = fmaf(WT, f3.x, acc[6]);                           \
                    acc[7] = fmaf(WT, f3.y, acc[7]);                           \
                }                                                              \
            }
            CORNER(x0,     y0,     w00)
            CORNER(x0 + 1, y0,     w01)
            CORNER(x0,     y0 + 1, w10)
            CORNER(x0 + 1, y0 + 1, w11)
#undef CORNER
        }
    }

    __nv_bfloat16 hb[8], lb[8];
#pragma unroll
    for (int k = 0; k < 8; k++) {
        __nv_bfloat16 hh = __float2bfloat16(acc[k]);
        hb[k] = hh;
        lb[k] = __float2bfloat16(acc[k] - __bfloat162float(hh));
    }
    size_t o = (size_t)bq * CDIM + bh * HDIM + sub * 8;
    *reinterpret_cast<uint4*>(g_pre_hi + o) = *reinterpret_cast<uint4*>(hb);
    *reinterpret_cast<uint4*>(g_pre_lo + o) = *reinterpret_cast<uint4*>(lb);
}

// ------------------------------ launch -------------------------------------
extern "C" void kernel_launch(void* const* d_in, const int* in_sizes, int n_in,
                              void* d_out, int out_size) {
    const float* query   = (const float*)d_in[0];
    const float* refpts  = (const float*)d_in[1];
    const float* inflat  = (const float*)d_in[2];
    const float* W_off   = (const float*)d_in[4];
    const float* b_off   = (const float*)d_in[5];
    const float* W_attn  = (const float*)d_in[6];
    const float* b_attn  = (const float*)d_in[7];
    const float* W_val   = (const float*)d_in[8];
    const float* b_val   = (const float*)d_in[9];
    const float* W_out   = (const float*)d_in[10];
    const float* b_out   = (const float*)d_in[11];
    float* out = (float*)d_out;

    void *qh, *ql, *ih, *il, *ph, *pl, *vh, *oap, *bcat;
    void *wvh, *wvl, *woh, *wol, *wuh, *wul;
    cudaGetSymbolAddress(&qh, g_q_hi);   cudaGetSymbolAddress(&ql, g_q_lo);
    cudaGetSymbolAddress(&ih, g_in_hi);  cudaGetSymbolAddress(&il, g_in_lo);
    cudaGetSymbolAddress(&ph, g_pre_hi); cudaGetSymbolAddress(&pl, g_pre_lo);
    cudaGetSymbolAddress(&vh, g_value_h);
    cudaGetSymbolAddress(&oap, g_offattn);
    cudaGetSymbolAddress(&bcat, g_bcat);
    cudaGetSymbolAddress(&wvh, g_wval_hi); cudaGetSymbolAddress(&wvl, g_wval_lo);
    cudaGetSymbolAddress(&woh, g_woa_hi);  cudaGetSymbolAddress(&wol, g_woa_lo);
    cudaGetSymbolAddress(&wuh, g_wout_hi); cudaGetSymbolAddress(&wul, g_wout_lo);

    const int smem = 2 * STAGE_SZ;   // 64 KB
    cudaFuncSetAttribute((const void*)hmma_gemm<0>,
                         cudaFuncAttributeMaxDynamicSharedMemorySize, smem);
    cudaFuncSetAttribute((const void*)hmma_gemm<1>,
                         cudaFuncAttributeMaxDynamicSharedMemorySize, smem);

    // ---- prep ----
    pack_bias<<<2, 256>>>(b_off, b_attn);
    pack_wt<<<(256 * 256 + 255) / 256, 256>>>(W_val, 256,
        (__nv_bfloat16*)wvh, (__nv_bfloat16*)wvl, 0);
    pack_wt<<<(256 * 256 + 255) / 256, 256>>>(W_out, 256,
        (__nv_bfloat16*)wuh, (__nv_bfloat16*)wul, 0);
    pack_wt<<<(256 * 256 + 255) / 256, 256>>>(W_off, 256,
        (__nv_bfloat16*)woh, (__nv_bfloat16*)wol, 0);
    pack_wt<<<(256 * 128 + 255) / 256, 256>>>(W_attn, 128,
        (__nv_bfloat16*)woh, (__nv_bfloat16*)wol, 256);

    const int n4 = MROWS * CDIM / 4;
    split_a<<<(n4 + 255) / 256, 256>>>((const float4*)query,
        (__nv_bfloat16*)qh, (__nv_bfloat16*)ql, n4);
    split_a<<<(n4 + 255) / 256, 256>>>((const float4*)inflat,
        (__nv_bfloat16*)ih, (__nv_bfloat16*)il, n4);

    const int mb = (MROWS + 127) / 128;   // 831

    // ---- value GEMM -> fp16 [M,256] ----
    hmma_gemm<1><<<dim3(2, mb), 256, smem>>>(
        (const __nv_bfloat16*)ih, (const __nv_bfloat16*)il,
        (const __nv_bfloat16*)wvh, (const __nv_bfloat16*)wvl,
        b_val, vh, MROWS, CDIM);

    // ---- off|attn GEMM -> fp32 [M,384] ----
    hmma_gemm<0><<<dim3(3, mb), 256, smem>>>(
        (const __nv_bfloat16*)qh, (const __nv_bfloat16*)ql,
        (const __nv_bfloat16*)woh, (const __nv_bfloat16*)wol,
        (const float*)bcat, oap, MROWS, NOA);

    // ---- sampling ----
    msda_sample<<<MROWS / WARPS_PER_BLK, 256>>>(refpts);

    // ---- out GEMM -> d_out fp32 [M,256] ----
    hmma_gemm<0><<<dim3(2, mb), 256, smem>>>(
        (const __nv_bfloat16*)ph, (const __nv_bfloat16*)pl,
        (const __nv_bfloat16*)wuh, (const __nv_bfloat16*)wul,
        b_out, out, MROWS, CDIM);
}

// round 6
// speedup vs baseline: 2.6701x; 1.0001x over previous
#include <cuda_runtime.h>
#include <cuda_fp16.h>
#include <cuda_bf16.h>
#include <cstdint>

// ---------------------------------------------------------------------------
// Multi-scale deformable attention — bf16 split GEMMs on mma.sync (HMMA).
// (tcgen05 unavailable: toolchain targets sm_100 without the 'a' feature set.)
// B=8, C=256, H=8, d=32, Lv=4, P=4, L=Nq=13294, M = 106352
//
//  split:   X = X_hi(bf16) + X_lo(bf16); A@B ~ Ahi*Bhi + Ahi*Blo + Alo*Bhi
//  Stage 1: value  = fp16(in @ W_val + b)         [M,256]
//  Stage 2: offattn = q @ [W_off|W_attn] + b      [M,384] fp32
//  Stage 3: sampling -> pre_hi/pre_lo (bf16)      [M,256]
//  Stage 4: out = pre @ W_out + b -> d_out        [M,256] fp32
// ---------------------------------------------------------------------------

#define BATCH 8
#define CDIM  256
#define NHEAD 8
#define HDIM  32
#define NLVL  4
#define NPNT  4
#define LTOT  13294
#define NQ    LTOT
#define MROWS (BATCH * NQ)     // 106352
#define NOA   384

// ------------------------------ device scratch -----------------------------
__device__ __align__(16) __nv_bfloat16 g_q_hi [(size_t)MROWS * CDIM];
__device__ __align__(16) __nv_bfloat16 g_q_lo [(size_t)MROWS * CDIM];
__device__ __align__(16) __nv_bfloat16 g_in_hi[(size_t)MROWS * CDIM];
__device__ __align__(16) __nv_bfloat16 g_in_lo[(size_t)MROWS * CDIM];
__device__ __align__(16) __nv_bfloat16 g_pre_hi[(size_t)MROWS * CDIM];
__device__ __align__(16) __nv_bfloat16 g_pre_lo[(size_t)MROWS * CDIM];
__device__ __align__(16) __half g_value_h[(size_t)MROWS * CDIM];
__device__ __align__(16) float  g_offattn[(size_t)MROWS * NOA];
// weights transposed to [N][K=256] bf16 hi/lo
__device__ __align__(16) __nv_bfloat16 g_wval_hi[CDIM * CDIM];
__device__ __align__(16) __nv_bfloat16 g_wval_lo[CDIM * CDIM];
__device__ __align__(16) __nv_bfloat16 g_woa_hi [NOA * CDIM];
__device__ __align__(16) __nv_bfloat16 g_woa_lo [NOA * CDIM];
__device__ __align__(16) __nv_bfloat16 g_wout_hi[CDIM * CDIM];
__device__ __align__(16) __nv_bfloat16 g_wout_lo[CDIM * CDIM];
__device__ __align__(16) float g_bcat[NOA];

// ------------------------------ PTX helpers --------------------------------
__device__ __forceinline__ uint32_t smem_u32(const void* p) {
    uint32_t a;
    asm("{ .reg .u64 t; cvta.to.shared.u64 t, %1; cvt.u32.u64 %0, t; }"
        : "=r"(a) : "l"(p));
    return a;
}

#define CP_ASYNC16(dst, src) \
    asm volatile("cp.async.cg.shared.global [%0], [%1], 16;" \
                 :: "r"(dst), "l"(src) : "memory")
#define CP_COMMIT() asm volatile("cp.async.commit_group;" ::: "memory")
#define CP_WAIT(n)  asm volatile("cp.async.wait_group %0;" :: "n"(n) : "memory")

#define LDSM_X4(r0, r1, r2, r3, a) \
    asm volatile("ldmatrix.sync.aligned.m8n8.x4.shared.b16 {%0,%1,%2,%3}, [%4];" \
                 : "=r"(r0), "=r"(r1), "=r"(r2), "=r"(r3) : "r"(a))

#define MMA16816(d, a0, a1, a2, a3, b0, b1)                                    \
    asm volatile("mma.sync.aligned.m16n8k16.row.col.f32.bf16.bf16.f32 "        \
                 "{%0,%1,%2,%3}, {%4,%5,%6,%7}, {%8,%9}, {%0,%1,%2,%3};"       \
                 : "+f"((d)[0]), "+f"((d)[1]), "+f"((d)[2]), "+f"((d)[3])      \
                 : "r"(a0), "r"(a1), "r"(a2), "r"(a3), "r"(b0), "r"(b1))

// 128B-line swizzle for 64B rows: two rows per line, 8 chunk slots/line.
// row r, chunk c (0..3, 16B each)
__device__ __forceinline__ uint32_t swz(int r, int c) {
    int slot = (((r & 1) << 2) | c) ^ ((r >> 1) & 7);
    return (uint32_t)(((r >> 1) << 7) + (slot << 4));
}

// ------------------------------ prep kernels -------------------------------
__global__ void pack_bias(const float* __restrict__ boff,
                          const float* __restrict__ battn) {
    int i = blockIdx.x * blockDim.x + threadIdx.x;
    if (i < NOA) g_bcat[i] = (i < 256) ? boff[i] : battn[i - 256];
}

// W [256 x Nsrc] row-major -> rows [rowoff..rowoff+Nsrc) of [N][256] hi/lo
__global__ void pack_wt(const float* __restrict__ W, int Nsrc,
                        __nv_bfloat16* __restrict__ hi,
                        __nv_bfloat16* __restrict__ lo, int rowoff) {
    int i = blockIdx.x * blockDim.x + threadIdx.x;
    if (i < 256 * Nsrc) {
        int k = i / Nsrc, n = i % Nsrc;
        float v = W[i];
        __nv_bfloat16 h = __float2bfloat16(v);
        hi[(size_t)(rowoff + n) * 256 + k] = h;
        lo[(size_t)(rowoff + n) * 256 + k] = __float2bfloat16(v - __bfloat162float(h));
    }
}

__global__ void split_a(const float4* __restrict__ src,
                        __nv_bfloat16* __restrict__ hi,
                        __nv_bfloat16* __restrict__ lo, int n4) {
    int i = blockIdx.x * blockDim.x + threadIdx.x;
    if (i >= n4) return;
    float4 v = src[i];
    __nv_bfloat16 h[4], l[4];
    float f[4] = {v.x, v.y, v.z, v.w};
#pragma unroll
    for (int k = 0; k < 4; k++) {
        h[k] = __float2bfloat16(f[k]);
        l[k] = __float2bfloat16(f[k] - __bfloat162float(h[k]));
    }
    *reinterpret_cast<uint2*>(hi + (size_t)i * 4) = *reinterpret_cast<uint2*>(h);
    *reinterpret_cast<uint2*>(lo + (size_t)i * 4) = *reinterpret_cast<uint2*>(l);
}

// ------------------------------ HMMA GEMM ----------------------------------
// C[128,128]-tile of (Ahi+Alo)[M,256] @ (Bhi+Blo)[N,256]^T + bias.
// A,B row-major [rows][256] bf16. grid = (N/128, ceil(M/128)).
// OUT_MODE: 0 = fp32, 1 = fp16.
#define TILE_SZ 8192                 // 128 rows x 32 bf16, swizzled
#define STAGE_SZ (4 * TILE_SZ)       // Ahi, Alo, Bhi, Blo

template<int OUT_MODE>
__global__ __launch_bounds__(256, 2)
void hmma_gemm(const __nv_bfloat16* __restrict__ Ahi,
               const __nv_bfloat16* __restrict__ Alo,
               const __nv_bfloat16* __restrict__ Bhi,
               const __nv_bfloat16* __restrict__ Blo,
               const float* __restrict__ bias,
               void* __restrict__ outp, int M, int ldOut) {
    extern __shared__ __align__(128) char smem[];
    const uint32_t sbase = smem_u32(smem);
    const int tid  = threadIdx.x;
    const int wid  = tid >> 5, lane = tid & 31;
    const int wm   = wid & 3, wn = wid >> 2;       // 4 x 2 warp grid
    const int bm   = blockIdx.y * 128;
    const int ncol0 = blockIdx.x * 128;
    const int rclA = M - 1;

    const __nv_bfloat16* gsrc[4] = {Ahi, Alo, Bhi, Blo};

    // per-thread load map: 2 chunks per tile (512 chunks, 256 threads)
    // chunk = tid + i*256 ; row = chunk>>2 ; c = chunk&3
    auto load_stage = [&](int buf, int kc) {
        const int kofs = kc * 32;
#pragma unroll
        for (int t = 0; t < 4; t++) {
            const __nv_bfloat16* gb = gsrc[t];
            const int row0 = (t < 2) ? bm : ncol0;
            const int rcl  = (t < 2) ? rclA : 0x7FFFFFFF;
            const uint32_t db = sbase + buf * STAGE_SZ + t * TILE_SZ;
#pragma unroll
            for (int i = 0; i < 2; i++) {
                int chunk = tid + i * 256;
                int row = chunk >> 2, c = chunk & 3;
                int gr = row0 + row; if (gr > rcl) gr = rcl;
                CP_ASYNC16(db + swz(row, c),
                           gb + (size_t)gr * 256 + kofs + c * 8);
            }
        }
    };

    float acc[2][8][4];
#pragma unroll
    for (int i = 0; i < 2; i++)
#pragma unroll
        for (int j = 0; j < 8; j++)
#pragma unroll
            for (int q = 0; q < 4; q++) acc[i][j][q] = 0.f;

    load_stage(0, 0);
    CP_COMMIT();

    for (int kc = 0; kc < 8; kc++) {
        const int buf = kc & 1;
        if (kc + 1 < 8) {
            load_stage(buf ^ 1, kc + 1);
            CP_COMMIT();
            CP_WAIT(1);
        } else {
            CP_WAIT(0);
        }
        __syncthreads();

        const uint32_t sAhi = sbase + buf * STAGE_SZ;
        const uint32_t sAlo = sAhi + TILE_SZ;
        const uint32_t sBhi = sAhi + 2 * TILE_SZ;
        const uint32_t sBlo = sAhi + 3 * TILE_SZ;

#pragma unroll
        for (int ks = 0; ks < 2; ks++) {
            // A fragments: 2 m-tiles x (hi, lo)
            uint32_t ahi[2][4], alo[2][4];
#pragma unroll
            for (int i = 0; i < 2; i++) {
                int row = wm * 32 + i * 16 + (lane & 15);
                int c   = ks * 2 + (lane >> 4);
                uint32_t off = swz(row, c);
                LDSM_X4(ahi[i][0], ahi[i][1], ahi[i][2], ahi[i][3], sAhi + off);
                LDSM_X4(alo[i][0], alo[i][1], alo[i][2], alo[i][3], sAlo + off);
            }
            // B: 4 pairs of n-tiles
#pragma unroll
            for (int jj = 0; jj < 4; jj++) {
                int g = lane >> 3, l8 = lane & 7;
                int row = wn * 64 + jj * 16 + ((g >> 1) << 3) + l8;
                int c   = ks * 2 + (g & 1);
                uint32_t off = swz(row, c);
                uint32_t bh0, bh1, bh2, bh3, bl0, bl1, bl2, bl3;
                LDSM_X4(bh0, bh1, bh2, bh3, sBhi + off);
                LDSM_X4(bl0, bl1, bl2, bl3, sBlo + off);
#pragma unroll
                for (int i = 0; i < 2; i++) {
                    MMA16816(acc[i][jj * 2],     ahi[i][0], ahi[i][1], ahi[i][2], ahi[i][3], bh0, bh1);
                    MMA16816(acc[i][jj * 2],     ahi[i][0], ahi[i][1], ahi[i][2], ahi[i][3], bl0, bl1);
                    MMA16816(acc[i][jj * 2],     alo[i][0], alo[i][1], alo[i][2], alo[i][3], bh0, bh1);
                    MMA16816(acc[i][jj * 2 + 1], ahi[i][0], ahi[i][1], ahi[i][2], ahi[i][3], bh2, bh3);
                    MMA16816(acc[i][jj * 2 + 1], ahi[i][0], ahi[i][1], ahi[i][2], ahi[i][3], bl2, bl3);
                    MMA16816(acc[i][jj * 2 + 1], alo[i][0], alo[i][1], alo[i][2], alo[i][3], bh2, bh3);
                }
            }
        }
        __syncthreads();
    }

    // ---- epilogue: direct global stores + bias ----
#pragma unroll
    for (int i = 0; i < 2; i++) {
        int r0 = bm + wm * 32 + i * 16 + (lane >> 2);
        int r1 = r0 + 8;
#pragma unroll
        for (int j = 0; j < 8; j++) {
            int gc = ncol0 + wn * 64 + j * 8 + (lane & 3) * 2;
            float b0 = __ldg(bias + gc), b1 = __ldg(bias + gc + 1);
            float v00 = acc[i][j][0] + b0, v01 = acc[i][j][1] + b1;
            float v10 = acc[i][j][2] + b0, v11 = acc[i][j][3] + b1;
            if (OUT_MODE == 1) {
                __half* o = (__half*)outp;
                if (r0 < M)
                    *reinterpret_cast<__half2*>(o + (size_t)r0 * ldOut + gc) =
                        __floats2half2_rn(v00, v01);
                if (r1 < M)
                    *reinterpret_cast<__half2*>(o + (size_t)r1 * ldOut + gc) =
                        __floats2half2_rn(v10, v11);
            } else {
                float* o = (float*)outp;
                if (r0 < M)
                    *reinterpret_cast<float2*>(o + (size_t)r0 * ldOut + gc) =
                        make_float2(v00, v01);
                if (r1 < M)
                    *reinterpret_cast<float2*>(o + (size_t)r1 * ldOut + gc) =
                        make_float2(v10, v11);
            }
        }
    }
}

// ------------------------------ sampler ------------------------------------
#define WARPS_PER_BLK 8
#define OFF_STRIDE 36
#define AW_STRIDE  20

__global__ __launch_bounds__(256)
void msda_sample(const float* __restrict__ refpts) {
    constexpr int WL[NLVL] = {100, 50, 25, 13};
    constexpr int HL[NLVL] = {100, 50, 25, 13};
    constexpr int ST[NLVL] = {0, 10000, 12500, 13125};
    const unsigned FULL = 0xFFFFFFFFu;

    __shared__ float off_s[WARPS_PER_BLK][NHEAD * OFF_STRIDE];
    __shared__ float aw_s [WARPS_PER_BLK][NHEAD * AW_STRIDE];

    const int w    = threadIdx.x >> 5;
    const int lane = threadIdx.x & 31;
    const int bq   = blockIdx.x * WARPS_PER_BLK + w;
    const int b    = bq / NQ;
    const int bh   = lane >> 2;
    const int sub  = lane & 3;

    const float* oa = g_offattn + (size_t)bq * NOA;

#pragma unroll
    for (int j0 = 0; j0 < 8; j0 += 4) {
        int o = lane * 8 + j0;
        float4 v = *reinterpret_cast<const float4*>(oa + o);
        float* dst = &off_s[w][(o >> 5) * OFF_STRIDE + (o & 31)];
        dst[0] = v.x; dst[1] = v.y; dst[2] = v.z; dst[3] = v.w;
    }
    {
        const float* lg = oa + 256 + bh * 16 + sub * 4;
        float l0 = lg[0], l1 = lg[1], l2 = lg[2], l3 = lg[3];
        float m = fmaxf(fmaxf(l0, l1), fmaxf(l2, l3));
        m = fmaxf(m, __shfl_xor_sync(FULL, m, 1));
        m = fmaxf(m, __shfl_xor_sync(FULL, m, 2));
        float e0 = __expf(l0 - m), e1 = __expf(l1 - m);
        float e2 = __expf(l2 - m), e3 = __expf(l3 - m);
        float s = e0 + e1 + e2 + e3;
        s += __shfl_xor_sync(FULL, s, 1);
        s += __shfl_xor_sync(FULL, s, 2);
        float inv = __frcp_rn(s);
        float* dst = &aw_s[w][bh * AW_STRIDE + sub * 4];
        dst[0] = e0 * inv; dst[1] = e1 * inv; dst[2] = e2 * inv; dst[3] = e3 * inv;
    }
    __syncwarp();

    float rpv = (lane < 8) ? __ldg(refpts + (size_t)bq * 8 + lane) : 0.f;

    const float* offp = &off_s[w][bh * OFF_STRIDE];
    const float* awp  = &aw_s[w][bh * AW_STRIDE];
    const __half* vhead = g_value_h + (size_t)b * ((size_t)LTOT * CDIM)
                        + bh * HDIM + sub * 8;

    float acc[8];
#pragma unroll
    for (int k = 0; k < 8; k++) acc[k] = 0.f;

#pragma unroll
    for (int l = 0; l < NLVL; l++) {
        const float rx = __shfl_sync(FULL, rpv, l * 2 + 0);
        const float ry = __shfl_sync(FULL, rpv, l * 2 + 1);
        const int Wl = WL[l], Hl = HL[l], lstart = ST[l];
        const float fW = (float)Wl, fH = (float)Hl;
#pragma unroll
        for (int p = 0; p < NPNT; p++) {
            const float ox = offp[l * 8 + p * 2 + 0];
            const float oy = offp[l * 8 + p * 2 + 1];
            const float a  = awp[l * 4 + p];

            float x = (rx + ox) * fW - 0.5f;
            float y = (ry + oy) * fH - 0.5f;
            float xf = floorf(x), yf = floorf(y);
            float fx = x - xf, fy = y - yf;
            int x0 = (int)xf, y0 = (int)yf;

            float ay0 = a * (1.f - fy), ay1 = a * fy;
            float w00 = ay0 * (1.f - fx), w01 = ay0 * fx;
            float w10 = ay1 * (1.f - fx), w11 = ay1 * fx;

#define CORNER(XI, YI, WT)                                                     \
            {                                                                  \
                int xi = (XI), yi = (YI);                                      \
                if ((unsigned)xi < (unsigned)Wl && (unsigned)yi < (unsigned)Hl) { \
                    const __half* p_ = vhead +                                 \
                        ((size_t)(lstart + yi * Wl + xi) << 8);                \
                    uint4 raw = *reinterpret_cast<const uint4*>(p_);           \
                    float2 f0 = __half22float2(*reinterpret_cast<__half2*>(&raw.x)); \
                    float2 f1 = __half22float2(*reinterpret_cast<__half2*>(&raw.y)); \
                    float2 f2 = __half22float2(*reinterpret_cast<__half2*>(&raw.z)); \
                    float2 f3 = __half22float2(*reinterpret_cast<__half2*>(&raw.w)); \
                    acc[0] = fmaf(WT, f0.x, acc[0]);                           \
                    acc[1] = fmaf(WT, f0.y, acc[1]);                           \
                    acc[2] = fmaf(WT, f1.x, acc[2]);                           \
                    acc[3] = fmaf(WT, f1.y, acc[3]);                           \
                    acc[4] = fmaf(WT, f2.x, acc[4]);                           \
                    acc[5] = fmaf(WT, f2.y, acc[5]);                           \
                    acc[6] = fmaf(WT, f3.x, acc[6]);                           \
                    acc[7] = fmaf(WT, f3.y, acc[7]);                           \
                }                                                              \
            }
            CORNER(x0,     y0,     w00)
            CORNER(x0 + 1, y0,     w01)
            CORNER(x0,     y0 + 1, w10)
            CORNER(x0 + 1, y0 + 1, w11)
#undef CORNER
        }
    }

    __nv_bfloat16 hb[8], lb[8];
#pragma unroll
    for (int k = 0; k < 8; k++) {
        __nv_bfloat16 hh = __float2bfloat16(acc[k]);
        hb[k] = hh;
        lb[k] = __float2bfloat16(acc[k] - __bfloat162float(hh));
    }
    size_t o = (size_t)bq * CDIM + bh * HDIM + sub * 8;
    *reinterpret_cast<uint4*>(g_pre_hi + o) = *reinterpret_cast<uint4*>(hb);
    *reinterpret_cast<uint4*>(g_pre_lo + o) = *reinterpret_cast<uint4*>(lb);
}

// ------------------------------ launch -------------------------------------
extern "C" void kernel_launch(void* const* d_in, const int* in_sizes, int n_in,
                              void* d_out, int out_size) {
    const float* query   = (const float*)d_in[0];
    const float* refpts  = (const float*)d_in[1];
    const float* inflat  = (const float*)d_in[2];
    const float* W_off   = (const float*)d_in[4];
    const float* b_off   = (const float*)d_in[5];
    const float* W_attn  = (const float*)d_in[6];
    const float* b_attn  = (const float*)d_in[7];
    const float* W_val   = (const float*)d_in[8];
    const float* b_val   = (const float*)d_in[9];
    const float* W_out   = (const float*)d_in[10];
    const float* b_out   = (const float*)d_in[11];
    float* out = (float*)d_out;

    void *qh, *ql, *ih, *il, *ph, *pl, *vh, *oap, *bcat;
    void *wvh, *wvl, *woh, *wol, *wuh, *wul;
    cudaGetSymbolAddress(&qh, g_q_hi);   cudaGetSymbolAddress(&ql, g_q_lo);
    cudaGetSymbolAddress(&ih, g_in_hi);  cudaGetSymbolAddress(&il, g_in_lo);
    cudaGetSymbolAddress(&ph, g_pre_hi); cudaGetSymbolAddress(&pl, g_pre_lo);
    cudaGetSymbolAddress(&vh, g_value_h);
    cudaGetSymbolAddress(&oap, g_offattn);
    cudaGetSymbolAddress(&bcat, g_bcat);
    cudaGetSymbolAddress(&wvh, g_wval_hi); cudaGetSymbolAddress(&wvl, g_wval_lo);
    cudaGetSymbolAddress(&woh, g_woa_hi);  cudaGetSymbolAddress(&wol, g_woa_lo);
    cudaGetSymbolAddress(&wuh, g_wout_hi); cudaGetSymbolAddress(&wul, g_wout_lo);

    const int smem = 2 * STAGE_SZ;   // 64 KB
    cudaFuncSetAttribute((const void*)hmma_gemm<0>,
                         cudaFuncAttributeMaxDynamicSharedMemorySize, smem);
    cudaFuncSetAttribute((const void*)hmma_gemm<1>,
                         cudaFuncAttributeMaxDynamicSharedMemorySize, smem);

    // ---- prep ----
    pack_bias<<<2, 256>>>(b_off, b_attn);
    pack_wt<<<(256 * 256 + 255) / 256, 256>>>(W_val, 256,
        (__nv_bfloat16*)wvh, (__nv_bfloat16*)wvl, 0);
    pack_wt<<<(256 * 256 + 255) / 256, 256>>>(W_out, 256,
        (__nv_bfloat16*)wuh, (__nv_bfloat16*)wul, 0);
    pack_wt<<<(256 * 256 + 255) / 256, 256>>>(W_off, 256,
        (__nv_bfloat16*)woh, (__nv_bfloat16*)wol, 0);
    pack_wt<<<(256 * 128 + 255) / 256, 256>>>(W_attn, 128,
        (__nv_bfloat16*)woh, (__nv_bfloat16*)wol, 256);

    const int n4 = MROWS * CDIM / 4;
    split_a<<<(n4 + 255) / 256, 256>>>((const float4*)query,
        (__nv_bfloat16*)qh, (__nv_bfloat16*)ql, n4);
    split_a<<<(n4 + 255) / 256, 256>>>((const float4*)inflat,
        (__nv_bfloat16*)ih, (__nv_bfloat16*)il, n4);

    const int mb = (MROWS + 127) / 128;   // 831

    // ---- value GEMM -> fp16 [M,256] ----
    hmma_gemm<1><<<dim3(2, mb), 256, smem>>>(
        (const __nv_bfloat16*)ih, (const __nv_bfloat16*)il,
        (const __nv_bfloat16*)wvh, (const __nv_bfloat16*)wvl,
        b_val, vh, MROWS, CDIM);

    // ---- off|attn GEMM -> fp32 [M,384] ----
    hmma_gemm<0><<<dim3(3, mb), 256, smem>>>(
        (const __nv_bfloat16*)qh, (const __nv_bfloat16*)ql,
        (const __nv_bfloat16*)woh, (const __nv_bfloat16*)wol,
        (const float*)bcat, oap, MROWS, NOA);

    // ---- sampling ----
    msda_sample<<<MROWS / WARPS_PER_BLK, 256>>>(refpts);

    // ---- out GEMM -> d_out fp32 [M,256] ----
    hmma_gemm<0><<<dim3(2, mb), 256, smem>>>(
        (const __nv_bfloat16*)ph, (const __nv_bfloat16*)pl,
        (const __nv_bfloat16*)wuh, (const __nv_bfloat16*)wul,
        b_out, out, MROWS, CDIM);
}